// round 13
// baseline (speedup 1.0000x reference)
#include <cuda_runtime.h>

typedef unsigned long long u64;

#define BB 8
#define CC 64
#define DD 32
#define HH 64
#define WW 64
#define SS (DD*HH*WW)      /* 131072 spatial per batch */
#define PLANE (HH*WW)      /* 4096 */
#define S4 (SS/4)          /* 32768 */
#define NPLANES (BB*DD)    /* 256 */
#define RED_UNITS (NPLANES*4)   /* quarter-plane work units */
#define CONV_UNITS 512          /* (b, dc, h-slab) CTA units  */
#define NRED 148                /* reducer CTAs (rest start as conv) */
#define NCTA 296                /* 2 per SM, all resident */

// Scratch: channel-reduced (avg,max) interleaved float2, [B][D][H][W].
__device__ __align__(16) float2 g_am[BB*SS];
__device__ unsigned g_rcnt;                 // reduce unit counter
__device__ unsigned g_ccnt;                 // conv unit counter
__device__ unsigned g_plane_cnt[NPLANES];   // 4 => plane ready

// ---------------------------------------------------------------------------
__global__ void zero_kernel() {
    int t = threadIdx.x;
    if (t < NPLANES) g_plane_cnt[t] = 0;
    if (t == 0) { g_rcnt = 0; g_ccnt = 0; }
}

// ---------------------------------------------------------------------------
// Packed f32x2 helpers (sm_103a; ptxas will NOT auto-fuse — must be PTX).
// ---------------------------------------------------------------------------
__device__ __forceinline__ u64 ffma2(u64 a, u64 b, u64 c) {
    u64 d;
    asm("fma.rn.f32x2 %0, %1, %2, %3;" : "=l"(d) : "l"(a), "l"(b), "l"(c));
    return d;
}
__device__ __forceinline__ u64 pack2(float lo, float hi) {
    u64 r;
    asm("mov.b64 %0, {%1, %2};" : "=l"(r) : "f"(lo), "f"(hi));
    return r;
}
__device__ __forceinline__ float2 unpack2(u64 v) {
    float2 f;
    asm("mov.b64 {%0, %1}, %2;" : "=f"(f.x), "=f"(f.y) : "l"(v));
    return f;
}

// ---------------------------------------------------------------------------
// Conv plane-step macro: accumulate plane p = d0-1+S into selected rotating
// accumulators. A0 -> out[p-1] (kd=2), A1 -> out[p] (kd=1), A2 -> out[p+1]
// (kd=0). Weights in registers (u64 packed (w_avg, w_max)).
// ---------------------------------------------------------------------------
#define PLANE_STEP(S, A0, A1, A2, POK)                                        \
  {                                                                           \
    aX2 = 0; aY2 = 0;                                                         \
    if (POK) {                                                                \
      const u64* pp = gam + (d0 - 1 + (S)) * PLANE + h * WW + wp;             \
      u64 v[3][4];                                                            \
      _Pragma("unroll")                                                       \
      for (int kh = 0; kh < 3; ++kh) {                                        \
        bool rok = (kh == 0) ? r0ok : ((kh == 2) ? r2ok : true);              \
        const u64* rp = pp + (kh - 1) * WW;                                   \
        v[kh][0] = (rok && c0ok) ? __ldg(rp - 1) : 0ULL;                      \
        v[kh][1] =  rok          ? __ldg(rp    ) : 0ULL;                      \
        v[kh][2] =  rok          ? __ldg(rp + 1) : 0ULL;                      \
        v[kh][3] = (rok && c3ok) ? __ldg(rp + 2) : 0ULL;                      \
      }                                                                       \
      _Pragma("unroll")                                                       \
      for (int kh = 0; kh < 3; ++kh) {                                        \
        _Pragma("unroll")                                                     \
        for (int kw = 0; kw < 3; ++kw) {                                      \
          const int i = kh * 3 + kw;                                          \
          u64 vx = v[kh][kw];                                                 \
          u64 vy = v[kh][kw + 1];                                             \
          if (A0) { aX0 = ffma2(vx, w2[18 + i], aX0);                         \
                    aY0 = ffma2(vy, w2[18 + i], aY0); }                       \
          if (A1) { aX1 = ffma2(vx, w2[ 9 + i], aX1);                         \
                    aY1 = ffma2(vy, w2[ 9 + i], aY1); }                       \
          if (A2) { aX2 = ffma2(vx, w2[     i], aX2);                         \
                    aY2 = ffma2(vy, w2[     i], aY2); }                       \
        }                                                                     \
      }                                                                       \
    }                                                                         \
  }

#define EMIT(S)                                                               \
  {                                                                           \
    int od = d0 + (S) - 2;                                                    \
    float2 fx = unpack2(aX0), fy = unpack2(aY0);                              \
    float2 o;                                                                 \
    o.x = 1.0f / (1.0f + __expf(-(fx.x + fx.y)));                             \
    o.y = 1.0f / (1.0f + __expf(-(fy.x + fy.y)));                             \
    *reinterpret_cast<float2*>(ob + od * PLANE + h * WW + wp) = o;            \
  }

#define ROT() { aX0 = aX1; aY0 = aY1; aX1 = aX2; aY1 = aY2; }

// ---------------------------------------------------------------------------
// Fused persistent kernel. 296 CTAs, all resident (2/SM, regs capped at 128
// by __launch_bounds__(256,2)). CTAs < NRED work-steal reduce units first,
// then everyone work-steals conv units. Conv units spin-wait (t0, nanosleep)
// on the per-plane ready counters, so conv streams behind the reduce frontier
// inside the DRAM-bound reduce window.
// ---------------------------------------------------------------------------
__global__ __launch_bounds__(256, 2) void fused_kernel(const float* __restrict__ x,
                                                       const float* __restrict__ Wt,
                                                       float* __restrict__ out) {
    int t = threadIdx.x;
    __shared__ unsigned s_unit;

    // ---------------- Phase 1: reduce (CTAs 0..NRED-1) ----------------
    if (blockIdx.x < NRED) {
        for (;;) {
            if (t == 0) s_unit = atomicAdd(&g_rcnt, 1);
            __syncthreads();
            unsigned u = s_unit;
            __syncthreads();
            if (u >= RED_UNITS) break;

            int p = u >> 2;            // plane index = b*32 + d
            int q = u & 3;             // quarter
            int b = p >> 5;
            int d = p & 31;
            int hw4 = q * 256 + t;     // float4 index within plane (0..1023)

            const float4* base = reinterpret_cast<const float4*>(x)
                               + ((size_t)(b * CC) * DD + d) * (PLANE / 4) + hw4;

            float4 s = make_float4(0.f, 0.f, 0.f, 0.f);
            float4 m = make_float4(-3.402823466e38f, -3.402823466e38f,
                                   -3.402823466e38f, -3.402823466e38f);
            #pragma unroll 8
            for (int c = 0; c < CC; ++c) {
                float4 v = __ldg(base + (size_t)c * S4);
                s.x += v.x; s.y += v.y; s.z += v.z; s.w += v.w;
                m.x = fmaxf(m.x, v.x); m.y = fmaxf(m.y, v.y);
                m.z = fmaxf(m.z, v.z); m.w = fmaxf(m.w, v.w);
            }
            const float inv = 1.0f / 64.0f;
            float4* o = reinterpret_cast<float4*>(
                g_am + (size_t)b * SS + (size_t)d * PLANE + (size_t)hw4 * 4);
            o[0] = make_float4(s.x * inv, m.x, s.y * inv, m.y);
            o[1] = make_float4(s.z * inv, m.z, s.w * inv, m.w);

            __threadfence();           // order STGs before the ready count
            __syncthreads();
            if (t == 0) atomicAdd(&g_plane_cnt[p], 1);
        }
    }

    // ---------------- Phase 2: conv (everyone; reducers join) ----------------
    // Packed weights in registers: w2[kd*9 + kh*3 + kw] = (W_avg, W_max)
    u64 w2[27];
    #pragma unroll
    for (int j = 0; j < 27; ++j)
        w2[j] = pack2(__ldg(Wt + j), __ldg(Wt + 27 + j));

    for (;;) {
        if (t == 0) s_unit = atomicAdd(&g_ccnt, 1);
        __syncthreads();
        unsigned v = s_unit;
        __syncthreads();
        if (v >= CONV_UNITS) break;

        int b   = v >> 6;          // batch
        int dc  = (v >> 3) & 7;    // d-chunk of 4
        int sub = v & 7;           // 8-row h slab
        int d0  = dc * 4;

        // t0 waits for the needed planes, barrier broadcasts readiness
        if (t == 0) {
            int plo = d0 ? d0 - 1 : 0;
            int phi = (d0 + 4 < DD) ? d0 + 4 : DD - 1;
            for (int pl = plo; pl <= phi; ++pl) {
                volatile unsigned* f = &g_plane_cnt[b * 32 + pl];
                while (*f < 4u) __nanosleep(128);
            }
            __threadfence();       // acquire: order flag read before data reads
        }
        __syncthreads();

        int h  = sub * 8 + (t >> 5);    // 0..63
        int wp = (t & 31) * 2;          // 0..62 even

        const u64* gam = reinterpret_cast<const u64*>(g_am) + (size_t)b * SS;
        float*     ob  = out + (size_t)b * SS;

        const bool r0ok = (h > 0), r2ok = (h < 63);
        const bool c0ok = (wp > 0), c3ok = (wp < 62);

        u64 aX0 = 0, aY0 = 0, aX1 = 0, aY1 = 0, aX2, aY2;

        PLANE_STEP(0, false, false, true,  (d0 > 0));          ROT();
        PLANE_STEP(1, false, true,  true,  true);              ROT();
        PLANE_STEP(2, true,  true,  true,  true);   EMIT(2);   ROT();
        PLANE_STEP(3, true,  true,  true,  true);   EMIT(3);   ROT();
        PLANE_STEP(4, true,  true,  false, true);   EMIT(4);   ROT();
        PLANE_STEP(5, true,  false, false, (d0 + 4 < DD));  EMIT(5);
    }
}

extern "C" void kernel_launch(void* const* d_in, const int* in_sizes, int n_in,
                              void* d_out, int out_size) {
    const float* x  = (const float*)d_in[0];   // [8,64,32,64,64] fp32
    const float* Wt = (const float*)d_in[1];   // [1,2,3,3,3]     fp32
    float* out = (float*)d_out;                // [8,1,32,64,64]  fp32
    (void)in_sizes; (void)n_in; (void)out_size;

    zero_kernel<<<1, 256>>>();
    fused_kernel<<<NCTA, 256>>>(x, Wt, out);
}

// round 14
// speedup vs baseline: 1.2671x; 1.2671x over previous
#include <cuda_runtime.h>

typedef unsigned long long u64;

#define BB 8
#define CC 64
#define DD 32
#define HH 64
#define WW 64
#define SS (DD*HH*WW)      /* 131072 spatial per batch */
#define PLANE (HH*WW)      /* 4096 */
#define S4 (SS/4)          /* 32768 */

// Scratch: channel-reduced (avg,max) interleaved float2, [B][D][H][W].
__device__ __align__(16) float2 g_am[BB*SS];

// ---------------------------------------------------------------------------
// Pass 1: channel mean + max. One thread = 4 consecutive w elements (float4).
// Measured ~6.6 TB/s — HBM path cap. Unchanged from r11.
// ---------------------------------------------------------------------------
__global__ __launch_bounds__(256) void reduce_kernel(const float* __restrict__ x) {
    int tid = blockIdx.x * blockDim.x + threadIdx.x;   // 0 .. 262143
    int b    = tid >> 15;
    int off4 = tid & (S4 - 1);

    const float4* base = reinterpret_cast<const float4*>(x)
                       + (size_t)b * CC * S4 + off4;

    float4 s = make_float4(0.f, 0.f, 0.f, 0.f);
    float4 m = make_float4(-3.402823466e38f, -3.402823466e38f,
                           -3.402823466e38f, -3.402823466e38f);

    #pragma unroll 8
    for (int c = 0; c < CC; ++c) {
        float4 v = __ldg(base + (size_t)c * S4);
        s.x += v.x; s.y += v.y; s.z += v.z; s.w += v.w;
        m.x = fmaxf(m.x, v.x); m.y = fmaxf(m.y, v.y);
        m.z = fmaxf(m.z, v.z); m.w = fmaxf(m.w, v.w);
    }

    const float inv = 1.0f / 64.0f;
    float4* o = reinterpret_cast<float4*>(g_am + (size_t)b * SS + 4 * (size_t)off4);
    o[0] = make_float4(s.x * inv, m.x, s.y * inv, m.y);
    o[1] = make_float4(s.z * inv, m.z, s.w * inv, m.w);
}

// ---------------------------------------------------------------------------
// Packed f32x2 helpers (sm_103a; ptxas will NOT auto-fuse — must be PTX).
// ---------------------------------------------------------------------------
__device__ __forceinline__ u64 ffma2(u64 a, u64 b, u64 c) {
    u64 d;
    asm("fma.rn.f32x2 %0, %1, %2, %3;" : "=l"(d) : "l"(a), "l"(b), "l"(c));
    return d;
}
__device__ __forceinline__ u64 pack2(float lo, float hi) {
    u64 r;
    asm("mov.b64 %0, {%1, %2};" : "=l"(r) : "f"(lo), "f"(hi));
    return r;
}
__device__ __forceinline__ float2 unpack2(u64 v) {
    float2 f;
    asm("mov.b64 {%0, %1}, %2;" : "=f"(f.x), "=f"(f.y) : "l"(v));
    return f;
}

// ---------------------------------------------------------------------------
// Pass 2: 3x3x3 SAME conv (avg,max -> 1 ch) + sigmoid.
// One thread = w-QUAD (4 consecutive outputs) x d-chunk of 4. Block 128,
// grid 512 (h-slab 8 x dc 8... x b). Sliding-plane rotation, compile-time
// accumulator trimming (27 fma2 per output = optimal). Row taps fetched as
// LDG.64 + 2x LDG.128 + LDG.64 (12 LDG per plane for 4 output columns).
// Weights in registers as packed (w_avg, w_max) u64.
// ---------------------------------------------------------------------------

// plane p = d0-1+S feeds: a0 -> out[p-1] (kd=2, w2[18+i]),
//                         a1 -> out[p]   (kd=1, w2[ 9+i]),
//                         a2 -> out[p+1] (kd=0, w2[    i])
#define QSTEP(S, E0, E1, E2, POK)                                             \
  {                                                                           \
    a2[0] = a2[1] = a2[2] = a2[3] = 0ULL;                                     \
    if (POK) {                                                                \
      const u64* pp = gam + (d0 - 1 + (S)) * PLANE + h * WW + wp;             \
      _Pragma("unroll")                                                       \
      for (int kh = 0; kh < 3; ++kh) {                                        \
        bool rok = (kh == 0) ? r0ok : ((kh == 2) ? r2ok : true);              \
        const u64* rp = pp + (kh - 1) * WW;                                   \
        u64 arr[6];                                                           \
        if (rok) {                                                            \
          ulonglong2 m01 = __ldg(reinterpret_cast<const ulonglong2*>(rp));    \
          ulonglong2 m23 = __ldg(reinterpret_cast<const ulonglong2*>(rp + 2));\
          arr[0] = wLok ? __ldg(rp - 1) : 0ULL;                               \
          arr[1] = m01.x; arr[2] = m01.y;                                     \
          arr[3] = m23.x; arr[4] = m23.y;                                     \
          arr[5] = wRok ? __ldg(rp + 4) : 0ULL;                               \
        } else {                                                              \
          arr[0] = arr[1] = arr[2] = arr[3] = arr[4] = arr[5] = 0ULL;         \
        }                                                                     \
        _Pragma("unroll")                                                     \
        for (int kw = 0; kw < 3; ++kw) {                                      \
          const int i = kh * 3 + kw;                                          \
          _Pragma("unroll")                                                   \
          for (int c = 0; c < 4; ++c) {                                       \
            u64 v = arr[c + kw];                                              \
            if (E0) a0[c] = ffma2(v, w2[18 + i], a0[c]);                      \
            if (E1) a1[c] = ffma2(v, w2[ 9 + i], a1[c]);                      \
            if (E2) a2[c] = ffma2(v, w2[     i], a2[c]);                      \
          }                                                                   \
        }                                                                     \
      }                                                                       \
    }                                                                         \
  }

#define EMIT(S)                                                               \
  {                                                                           \
    int od = d0 + (S) - 2;                                                    \
    float4 o;                                                                 \
    { float2 f = unpack2(a0[0]); o.x = 1.0f / (1.0f + __expf(-(f.x + f.y))); }\
    { float2 f = unpack2(a0[1]); o.y = 1.0f / (1.0f + __expf(-(f.x + f.y))); }\
    { float2 f = unpack2(a0[2]); o.z = 1.0f / (1.0f + __expf(-(f.x + f.y))); }\
    { float2 f = unpack2(a0[3]); o.w = 1.0f / (1.0f + __expf(-(f.x + f.y))); }\
    *reinterpret_cast<float4*>(ob + od * PLANE + h * WW + wp) = o;            \
  }

#define ROT()                                                                 \
  { a0[0] = a1[0]; a0[1] = a1[1]; a0[2] = a1[2]; a0[3] = a1[3];               \
    a1[0] = a2[0]; a1[1] = a2[1]; a1[2] = a2[2]; a1[3] = a2[3]; }

__global__ __launch_bounds__(128, 4) void conv_kernel(const float* __restrict__ Wt,
                                                      float* __restrict__ out) {
    int t   = threadIdx.x;
    int blk = blockIdx.x;        // 0..511
    int sub = blk & 7;           // h slab (8 rows)
    int dc  = (blk >> 3) & 7;    // d chunk of 4
    int b   = blk >> 6;          // batch
    int d0  = dc * 4;

    int wp = (t & 15) * 4;       // 0,4,...,60  (quad of w outputs)
    int h  = sub * 8 + (t >> 4); // 0..63

    // Packed weights: w2[kd*9 + kh*3 + kw] = (W_avg, W_max)
    u64 w2[27];
    #pragma unroll
    for (int j = 0; j < 27; ++j)
        w2[j] = pack2(__ldg(Wt + j), __ldg(Wt + 27 + j));

    const u64* gam = reinterpret_cast<const u64*>(g_am) + (size_t)b * SS;
    float*     ob  = out + (size_t)b * SS;

    const bool r0ok = (h > 0), r2ok = (h < 63);
    const bool wLok = (wp > 0), wRok = (wp < 60);

    u64 a0[4] = {0,0,0,0}, a1[4] = {0,0,0,0}, a2[4];

    QSTEP(0, false, false, true,  (d0 > 0));          ROT();
    QSTEP(1, false, true,  true,  true);              ROT();
    QSTEP(2, true,  true,  true,  true);   EMIT(2);   ROT();
    QSTEP(3, true,  true,  true,  true);   EMIT(3);   ROT();
    QSTEP(4, true,  true,  false, true);   EMIT(4);   ROT();
    QSTEP(5, true,  false, false, (d0 + 4 < DD));  EMIT(5);
}

extern "C" void kernel_launch(void* const* d_in, const int* in_sizes, int n_in,
                              void* d_out, int out_size) {
    const float* x  = (const float*)d_in[0];   // [8,64,32,64,64] fp32
    const float* Wt = (const float*)d_in[1];   // [1,2,3,3,3]     fp32
    float* out = (float*)d_out;                // [8,1,32,64,64]  fp32
    (void)in_sizes; (void)n_in; (void)out_size;

    reduce_kernel<<<1024, 256>>>(x);
    conv_kernel<<<512, 128>>>(Wt, out);
}